// round 6
// baseline (speedup 1.0000x reference)
#include <cuda_runtime.h>

// NablaT 3D: out[z,y,x] = bdiff_z(x0) + bdiff_y(x1) + bdiff_x(x2)
// bdiff along dim d: out[i] = a - b, a = (i>0)? v[i-1] : 0, b = (i<S-1)? v[i] : 0
//
// x: [3, 320, 320, 320] fp32. out: [320,320,320] fp32. Traffic floor 524 MB.
// Best-measured geometry (R1): grid (1,80,320) x block (80,4) -> zero div/mod,
// zero bounds checks. Plus: warp-shuffle left halo (lane 0 only loads the
// scalar), __ldcs on the read-once x2 stream, __stcs on the write-once output.

#define S 320
#define PLANE (S * S)           // 102400
#define VOL   (S * S * S)       // 32768000
#define X4    (S / 4)           // 80
#define P4    (PLANE / 4)       // 25600

__global__ __launch_bounds__(320)
void nablat_kernel(const float* __restrict__ xin, float* __restrict__ out) {
    const unsigned x4 = threadIdx.x;                        // 0..79
    const unsigned y  = blockIdx.y * 4u + threadIdx.y;      // 0..319
    const unsigned z  = blockIdx.z;                         // 0..319

    const unsigned t = z * (unsigned)P4 + y * (unsigned)X4 + x4;  // flat float4 index

    const float4* __restrict__ p0 = (const float4*)(xin);
    const float4* __restrict__ p1 = p0 + (unsigned)(VOL / 4);
    const float4* __restrict__ p2 = p0 + 2u * (unsigned)(VOL / 4);
    const float*  __restrict__ s2 = (const float*)p2;

    const float4 zero = make_float4(0.f, 0.f, 0.f, 0.f);

    // axis 0 (z): a0 = x0[z-1], b0 = x0[z] (b zeroed at z==S-1)
    float4 a0 = (z > 0)     ? __ldg(&p0[t - P4]) : zero;
    float4 b0 = (z < S - 1) ? __ldg(&p0[t])      : zero;

    // axis 1 (y): a1 = x1[y-1], b1 = x1[y]
    float4 a1 = (y > 0)     ? __ldg(&p1[t - X4]) : zero;
    float4 b1 = (y < S - 1) ? __ldg(&p1[t])      : zero;

    // axis 2 (x): read-once stream -> evict-first; left halo via shuffle.
    float4 v2 = __ldcs(&p2[t]);

    // flat-1 within the block is the x-neighbor whenever x4>0
    // (flat = tid.y*80 + tid.x, so x4>0 => no row crossing).
    const unsigned lane = (threadIdx.y * 80u + threadIdx.x) & 31u;
    float prev = __shfl_up_sync(0xffffffffu, v2.w, 1);
    if (lane == 0 && x4 > 0)   // warp edge: fetch the one scalar we can't shuffle
        prev = __ldg(&s2[t * 4u - 1u]);
    if (x4 == 0)               // x == 0 boundary: a = 0
        prev = 0.f;

    const float b2w = (x4 == X4 - 1) ? 0.f : v2.w;   // x == S-1 boundary

    float4 o;
    o.x = (a0.x - b0.x) + (a1.x - b1.x) + (prev - v2.x);
    o.y = (a0.y - b0.y) + (a1.y - b1.y) + (v2.x - v2.y);
    o.z = (a0.z - b0.z) + (a1.z - b1.z) + (v2.y - v2.z);
    o.w = (a0.w - b0.w) + (a1.w - b1.w) + (v2.z - b2w);

    __stcs(&((float4*)out)[t], o);   // streaming: output never re-read
}

extern "C" void kernel_launch(void* const* d_in, const int* in_sizes, int n_in,
                              void* d_out, int out_size) {
    const float* x = (const float*)d_in[0];
    float* out = (float*)d_out;

    dim3 block(X4, 4, 1);        // 320 threads
    dim3 grid(1, S / 4, S);      // (1, 80, 320)
    nablat_kernel<<<grid, block>>>(x, out);
}

// round 7
// speedup vs baseline: 1.0163x; 1.0163x over previous
#include <cuda_runtime.h>

// NablaT 3D: out[z,y,x] = bdiff_z(x0) + bdiff_y(x1) + bdiff_x(x2)
// bdiff along dim d: out[0] = -v[0]; out[i] = v[i-1] - v[i]; out[S-1] = v[S-2]
// i.e. out[i] = a - b with a = (i>0)? v[i-1] : 0, b = (i<S-1)? v[i] : 0.
//
// x: [3, 320, 320, 320] fp32 contiguous. out: [320,320,320] fp32.
// Measured-best shape (R1): one thread per float4, grid (1,80,320) x block (80,4)
// -> zero div/mod, zero bounds checks, 32 regs, best HBM (6.98 TB/s, 87% of spec),
// traffic at the 524 MB floor. Single addition: __stcs streaming store
// (output is write-once; keeps L2 for the z-1/y-1 halo dedup).

#define S 320
#define PLANE (S * S)           // 102400
#define VOL (S * S * S)         // 32768000
#define X4 (S / 4)              // 80 float4 per row

__global__ __launch_bounds__(320, 4)
void nablat_kernel(const float* __restrict__ xin, float* __restrict__ out) {
    const int x4 = threadIdx.x;                           // 0..79
    const int y  = blockIdx.y * blockDim.y + threadIdx.y; // 0..319
    const int z  = blockIdx.z;                            // 0..319
    const int xi = x4 * 4;

    const long base = (long)z * PLANE + (long)y * S + xi;
    const long b4   = base >> 2;

    const float4* __restrict__ p0 = (const float4*)(xin);
    const float4* __restrict__ p1 = (const float4*)(xin + (long)VOL);
    const float4* __restrict__ p2 = (const float4*)(xin + 2L * VOL);
    const float*  __restrict__ s2 = xin + 2L * VOL;

    const float4 zero = make_float4(0.f, 0.f, 0.f, 0.f);

    // axis 0 (z): a0 = x0[z-1], b0 = x0[z] (b zeroed at z==S-1)
    float4 b0 = (z < S - 1) ? __ldg(&p0[b4])             : zero;
    float4 a0 = (z > 0)     ? __ldg(&p0[b4 - PLANE / 4]) : zero;

    // axis 1 (y): a1 = x1[y-1], b1 = x1[y]
    float4 b1 = (y < S - 1) ? __ldg(&p1[b4])             : zero;
    float4 a1 = (y > 0)     ? __ldg(&p1[b4 - S / 4])     : zero;

    // axis 2 (x): within-vector shift; halo element at xi-1
    float4 v2   = __ldg(&p2[b4]);
    float  prev = (xi > 0) ? __ldg(&s2[base - 1]) : 0.f;
    // last lane of last vector in a row: b = 0 (x == S-1)
    float b2w = (x4 == X4 - 1) ? 0.f : v2.w;

    float4 o;
    o.x = (a0.x - b0.x) + (a1.x - b1.x) + (prev - v2.x);
    o.y = (a0.y - b0.y) + (a1.y - b1.y) + (v2.x - v2.y);
    o.z = (a0.z - b0.z) + (a1.z - b1.z) + (v2.y - v2.z);
    o.w = (a0.w - b0.w) + (a1.w - b1.w) + (v2.z - b2w);

    __stcs(&((float4*)out)[b4], o);   // streaming: output never re-read
}

extern "C" void kernel_launch(void* const* d_in, const int* in_sizes, int n_in,
                              void* d_out, int out_size) {
    const float* x = (const float*)d_in[0];
    float* out = (float*)d_out;

    dim3 block(X4, 4, 1);        // 320 threads: one thread per float4, 4 rows
    dim3 grid(1, S / 4, S);      // (1, 80, 320)
    nablat_kernel<<<grid, block>>>(x, out);
}

// round 8
// speedup vs baseline: 1.0189x; 1.0025x over previous
#include <cuda_runtime.h>

// NablaT 3D: out[z,y,x] = bdiff_z(x0) + bdiff_y(x1) + bdiff_x(x2)
// bdiff along dim d: out[i] = a - b, a = (i>0)? v[i-1] : 0, b = (i<S-1)? v[i] : 0
//
// x: [3, 320, 320, 320] fp32. out: [320,320,320] fp32. Traffic floor 524 MB.
// Final form: R3's flat 256-thread geometry (best measured wall time, 100%
// theoretical occupancy at 32 regs, exact-fit grid) + __stcs streaming store
// (output is write-once; evict-first keeps L2 for the z-1/y-1 halo dedup).
// All other micro-variants (z-unroll, shuffle halo, __ldcs, 512-blocks)
// measured neutral-or-worse across R2-R7; kernel is at the HBM roofline
// (~87% of 8 TB/s spec, DRAM-active ~87%).

#define S 320
#define PLANE (S * S)           // 102400
#define VOL   (S * S * S)       // 32768000
#define X4    (S / 4)           // 80
#define P4    (PLANE / 4)       // 25600
#define NV4   (VOL / 4)         // 8192000 float4 outputs

__global__ __launch_bounds__(256)
void nablat_kernel(const float* __restrict__ xin, float* __restrict__ out) {
    const unsigned t = blockIdx.x * 256u + threadIdx.x;  // flat float4 index == [z,y,x4]

    const unsigned x4  = t % X4;
    const unsigned rem = t / X4;
    const unsigned y   = rem % S;
    const unsigned z   = rem / S;
    const unsigned xi  = x4 * 4;

    const float4* __restrict__ p0 = (const float4*)(xin);
    const float4* __restrict__ p1 = (const float4*)(xin + (long)VOL);
    const float4* __restrict__ p2 = (const float4*)(xin + 2L * VOL);
    const float*  __restrict__ s2 = xin + 2L * VOL;

    const float4 zero = make_float4(0.f, 0.f, 0.f, 0.f);

    // axis 0 (z): a0 = x0[z-1], b0 = x0[z] (b zeroed at z==S-1)
    float4 b0 = (z < S - 1) ? __ldg(&p0[t])      : zero;
    float4 a0 = (z > 0)     ? __ldg(&p0[t - P4]) : zero;

    // axis 1 (y): a1 = x1[y-1], b1 = x1[y]
    float4 b1 = (y < S - 1) ? __ldg(&p1[t])      : zero;
    float4 a1 = (y > 0)     ? __ldg(&p1[t - X4]) : zero;

    // axis 2 (x): within-vector shift; left-halo scalar at xi-1 (L1/L2 hit)
    float4 v2   = __ldg(&p2[t]);
    float  prev = (xi > 0) ? __ldg(&s2[(long)t * 4 - 1]) : 0.f;
    float  b2w  = (x4 == X4 - 1) ? 0.f : v2.w;   // x == S-1 boundary

    float4 o;
    o.x = (a0.x - b0.x) + (a1.x - b1.x) + (prev - v2.x);
    o.y = (a0.y - b0.y) + (a1.y - b1.y) + (v2.x - v2.y);
    o.z = (a0.z - b0.z) + (a1.z - b1.z) + (v2.y - v2.z);
    o.w = (a0.w - b0.w) + (a1.w - b1.w) + (v2.z - b2w);

    __stcs(&((float4*)out)[t], o);   // streaming: output never re-read
}

extern "C" void kernel_launch(void* const* d_in, const int* in_sizes, int n_in,
                              void* d_out, int out_size) {
    const float* x = (const float*)d_in[0];
    float* out = (float*)d_out;

    nablat_kernel<<<NV4 / 256, 256>>>(x, out);   // 32000 blocks, exact fit
}